// round 12
// baseline (speedup 1.0000x reference)
#include <cuda_runtime.h>

#define NFEAT 64
#define MAX_GRAPHS 16384
#define PERSIST_BLOCKS (152 * 12)   // one wave on GB300 (152 SMs x 12 blocks)

// seg_start[g] = first row i with idx[i] >= g. (+1 sentinel entry)
__device__ int g_seg_start[MAX_GRAPHS + 1];

// Vectorized boundary finder: each thread owns 4 consecutive idx values.
__global__ void bounds_kernel(const int* __restrict__ idx, int n, int num_graphs) {
    int t = blockIdx.x * blockDim.x + threadIdx.x;
    int base = t * 4;
    if (base >= n) return;

    int prev = (base > 0) ? __ldg(idx + base - 1) : -1;

    int vals[4];
    if (base + 3 < n) {
        int4 v = __ldg(reinterpret_cast<const int4*>(idx) + t);
        vals[0] = v.x; vals[1] = v.y; vals[2] = v.z; vals[3] = v.w;
    } else {
        #pragma unroll
        for (int j = 0; j < 4; ++j)
            vals[j] = (base + j < n) ? __ldg(idx + base + j) : 0;
    }

    #pragma unroll
    for (int j = 0; j < 4; ++j) {
        int e = base + j;
        if (e >= n) break;
        int cur = vals[j];
        for (int g = prev + 1; g <= cur; ++g)
            g_seg_start[g] = e;
        if (e == n - 1)
            for (int g = cur + 1; g <= num_graphs; ++g)
                g_seg_start[g] = n;
        prev = cur;
    }
}

// out[g,f] = (sum_seg x*exp(x)) / (sum_seg exp(x)).
// SINGLE-WAVE PERSISTENT: 1824 blocks (one per SM slot), each loops over
// ~9 graphs (g = bid, bid+1824, ...). Inside a graph: 4 warps stream row
// PAIRS via one LDG.128 per lane (512B/warp/instr); lanes 0-15 even row,
// 16-31 odd row; lane owns features 4*(l&15)..+3. Eliminates all wave
// transitions and averages segment-length variance across ~9 segments.
__global__ __launch_bounds__(128, 12) void readout_kernel(
    const float* __restrict__ feat,
    float*       __restrict__ out,
    int num_graphs)
{
    const int lane = threadIdx.x & 31;
    const int w    = threadIdx.x >> 5;   // warp 0..3
    const unsigned FULL = 0xffffffffu;

    __shared__ float4 s_e[4][16];
    __shared__ float4 s_w[4][16];

    const float4* __restrict__ f4 = reinterpret_cast<const float4*>(feat);

    for (int g = blockIdx.x; g < num_graphs; g += gridDim.x) {
        const int start = __ldg(&g_seg_start[g]);
        const int end   = __ldg(&g_seg_start[g + 1]);

        float4 e_acc = make_float4(0.f, 0.f, 0.f, 0.f);
        float4 w_acc = make_float4(0.f, 0.f, 0.f, 0.f);

        #pragma unroll 4
        for (int r = start + 2 * w; r + 1 < end; r += 8) {
            float4 v = __ldcs(f4 + (size_t)r * (NFEAT / 4) + lane);
            float a = __expf(v.x), b = __expf(v.y);
            float c = __expf(v.z), d = __expf(v.w);
            e_acc.x += a;       e_acc.y += b;
            e_acc.z += c;       e_acc.w += d;
            w_acc.x += v.x * a; w_acc.y += v.y * b;
            w_acc.z += v.z * c; w_acc.w += v.w * d;
        }

        // Fold lanes 16-31 (odd row of pair, same features) into lanes 0-15.
        e_acc.x += __shfl_down_sync(FULL, e_acc.x, 16);
        e_acc.y += __shfl_down_sync(FULL, e_acc.y, 16);
        e_acc.z += __shfl_down_sync(FULL, e_acc.z, 16);
        e_acc.w += __shfl_down_sync(FULL, e_acc.w, 16);
        w_acc.x += __shfl_down_sync(FULL, w_acc.x, 16);
        w_acc.y += __shfl_down_sync(FULL, w_acc.y, 16);
        w_acc.z += __shfl_down_sync(FULL, w_acc.z, 16);
        w_acc.w += __shfl_down_sync(FULL, w_acc.w, 16);

        if (lane < 16) {
            s_e[w][lane] = e_acc;
            s_w[w][lane] = w_acc;
        }
        __syncthreads();

        if (threadIdx.x < NFEAT) {
            const int f = threadIdx.x;
            const float* se = reinterpret_cast<const float*>(s_e);
            const float* sw = reinterpret_cast<const float*>(s_w);
            float d = se[0 * NFEAT + f] + se[1 * NFEAT + f] + se[2 * NFEAT + f] + se[3 * NFEAT + f];
            float n = sw[0 * NFEAT + f] + sw[1 * NFEAT + f] + sw[2 * NFEAT + f] + sw[3 * NFEAT + f];

            // Odd leftover row: one coalesced LDG.32 per thread.
            if ((end - start) & 1) {
                float x = __ldcs(feat + (size_t)(end - 1) * NFEAT + f);
                float e = __expf(x);
                d += e;
                n += x * e;
            }
            out[(size_t)g * NFEAT + f] = (d != 0.f) ? (n / d) : 0.f;
        }
        __syncthreads();   // protect smem reuse for the next graph
    }
}

extern "C" void kernel_launch(void* const* d_in, const int* in_sizes, int n_in,
                              void* d_out, int out_size) {
    const float* feat = (const float*)d_in[0];   // (N_atoms, 64) float32
    const int*   idx  = (const int*)d_in[1];     // (N_atoms,)    int32, sorted
    float*       out  = (float*)d_out;           // (G, 64)       float32

    const int n_atoms    = in_sizes[1];
    const int num_graphs = out_size / NFEAT;

    int bthreads = (n_atoms + 3) / 4;
    bounds_kernel<<<(bthreads + 255) / 256, 256>>>(idx, n_atoms, num_graphs);

    int grid = (num_graphs < PERSIST_BLOCKS) ? num_graphs : PERSIST_BLOCKS;
    readout_kernel<<<grid, 128>>>(feat, out, num_graphs);
}

// round 13
// speedup vs baseline: 1.0976x; 1.0976x over previous
#include <cuda_runtime.h>

#define NFEAT 64
#define MAX_GRAPHS 16384

// seg_start[g] = first row i with idx[i] >= g. (+1 sentinel entry)
__device__ int g_seg_start[MAX_GRAPHS + 1];

// Vectorized boundary finder: each thread owns 8 consecutive idx values
// (2x int4). Writes seg_start[g]=e at every step of the sorted sequence.
__global__ void bounds_kernel(const int* __restrict__ idx, int n, int num_graphs) {
    int t = blockIdx.x * blockDim.x + threadIdx.x;
    int base = t * 8;
    if (base >= n) return;

    int prev = (base > 0) ? __ldg(idx + base - 1) : -1;

    int vals[8];
    if (base + 7 < n) {
        int4 v0 = __ldg(reinterpret_cast<const int4*>(idx) + 2 * t);
        int4 v1 = __ldg(reinterpret_cast<const int4*>(idx) + 2 * t + 1);
        vals[0] = v0.x; vals[1] = v0.y; vals[2] = v0.z; vals[3] = v0.w;
        vals[4] = v1.x; vals[5] = v1.y; vals[6] = v1.z; vals[7] = v1.w;
    } else {
        #pragma unroll
        for (int j = 0; j < 8; ++j)
            vals[j] = (base + j < n) ? __ldg(idx + base + j) : 0;
    }

    #pragma unroll
    for (int j = 0; j < 8; ++j) {
        int e = base + j;
        if (e >= n) break;
        int cur = vals[j];
        for (int g = prev + 1; g <= cur; ++g)
            g_seg_start[g] = e;
        if (e == n - 1)                       // trailing sentinel(s)
            for (int g = cur + 1; g <= num_graphs; ++g)
                g_seg_start[g] = n;
        prev = cur;
    }
}

// out[g,f] = (sum_seg x*exp(x)) / (sum_seg exp(x)).
// One block / graph; 4 warps; each warp streams TWO rows per iteration via
// one LDG.128 per lane (512B/warp/instr). Lanes 0-15: even row of the pair,
// 16-31: odd row; lane owns features 4*(l&15)..+3. __ldcs since feat is
// single-use. Odd leftover row is folded into the final 64-thread phase.
// (This exact config is the measured best: DRAM 81.5%, main 80.2us.)
__global__ __launch_bounds__(128, 12) void readout_kernel(
    const float* __restrict__ feat,
    float*       __restrict__ out)
{
    const int g     = blockIdx.x;
    const int start = __ldg(&g_seg_start[g]);
    const int end   = __ldg(&g_seg_start[g + 1]);

    const int lane = threadIdx.x & 31;
    const int w    = threadIdx.x >> 5;   // warp 0..3

    float4 e_acc = make_float4(0.f, 0.f, 0.f, 0.f);
    float4 w_acc = make_float4(0.f, 0.f, 0.f, 0.f);

    // Row pair (r, r+1) viewed as 512B = 32 lanes * float4.
    const float4* __restrict__ f4 = reinterpret_cast<const float4*>(feat);

    #pragma unroll 4
    for (int r = start + 2 * w; r + 1 < end; r += 8) {
        float4 v = __ldcs(f4 + (size_t)r * (NFEAT / 4) + lane);
        float e0 = __expf(v.x), e1 = __expf(v.y);
        float e2 = __expf(v.z), e3 = __expf(v.w);
        e_acc.x += e0;       e_acc.y += e1;
        e_acc.z += e2;       e_acc.w += e3;
        w_acc.x += v.x * e0; w_acc.y += v.y * e1;
        w_acc.z += v.z * e2; w_acc.w += v.w * e3;
    }

    // Fold lanes 16-31 (odd row of pair, same features) into lanes 0-15.
    const unsigned FULL = 0xffffffffu;
    e_acc.x += __shfl_down_sync(FULL, e_acc.x, 16);
    e_acc.y += __shfl_down_sync(FULL, e_acc.y, 16);
    e_acc.z += __shfl_down_sync(FULL, e_acc.z, 16);
    e_acc.w += __shfl_down_sync(FULL, e_acc.w, 16);
    w_acc.x += __shfl_down_sync(FULL, w_acc.x, 16);
    w_acc.y += __shfl_down_sync(FULL, w_acc.y, 16);
    w_acc.z += __shfl_down_sync(FULL, w_acc.z, 16);
    w_acc.w += __shfl_down_sync(FULL, w_acc.w, 16);

    __shared__ float4 s_e[4][16];
    __shared__ float4 s_w[4][16];
    if (lane < 16) {
        s_e[w][lane] = e_acc;
        s_w[w][lane] = w_acc;
    }
    __syncthreads();

    if (threadIdx.x < NFEAT) {
        const int f = threadIdx.x;
        const float* se = reinterpret_cast<const float*>(s_e);
        const float* sw = reinterpret_cast<const float*>(s_w);
        float d = se[0 * NFEAT + f] + se[1 * NFEAT + f] + se[2 * NFEAT + f] + se[3 * NFEAT + f];
        float n = sw[0 * NFEAT + f] + sw[1 * NFEAT + f] + sw[2 * NFEAT + f] + sw[3 * NFEAT + f];

        // Odd leftover row: one coalesced LDG.32 per thread.
        if ((end - start) & 1) {
            float x = __ldcs(feat + (size_t)(end - 1) * NFEAT + f);
            float e = __expf(x);
            d += e;
            n += x * e;
        }
        out[(size_t)g * NFEAT + f] = (d != 0.f) ? (n / d) : 0.f;
    }
}

extern "C" void kernel_launch(void* const* d_in, const int* in_sizes, int n_in,
                              void* d_out, int out_size) {
    const float* feat = (const float*)d_in[0];   // (N_atoms, 64) float32
    const int*   idx  = (const int*)d_in[1];     // (N_atoms,)    int32, sorted
    float*       out  = (float*)d_out;           // (G, 64)       float32

    const int n_atoms    = in_sizes[1];
    const int num_graphs = out_size / NFEAT;

    int bthreads = (n_atoms + 7) / 8;
    bounds_kernel<<<(bthreads + 511) / 512, 512>>>(idx, n_atoms, num_graphs);
    readout_kernel<<<num_graphs, 128>>>(feat, out);
}